// round 1
// baseline (speedup 1.0000x reference)
#include <cuda_runtime.h>
#include <math_constants.h>

// piecewise_maxpool: conv_output [B=4096, S=256, F=256] f32, e1/e2 [B] i32
// out [B, 3*F]: seg0 = max over s in [0, e1], seg1 = (e1, e2], seg2 = (e2, S)
// Segments are guaranteed non-empty by input construction.

static constexpr int BATCH = 4096;
static constexpr int SEQ   = 256;
static constexpr int FILT  = 256;   // 64 float4 per position

__device__ __forceinline__ float4 fmax4(float4 a, float4 b) {
    return make_float4(fmaxf(a.x, b.x), fmaxf(a.y, b.y),
                       fmaxf(a.z, b.z), fmaxf(a.w, b.w));
}

__global__ __launch_bounds__(256, 8)
void piecewise_maxpool_kernel(const float* __restrict__ x,
                              const int*   __restrict__ e1,
                              const int*   __restrict__ e2,
                              float*       __restrict__ out)
{
    const int b = blockIdx.x;
    const int t = threadIdx.x;
    const int g = t & 63;    // float4 group within filter dim (filters 4g..4g+3)
    const int p = t >> 6;    // position sub-offset 0..3

    const int c1 = __ldg(&e1[b]);
    const int c2 = __ldg(&e2[b]);

    const float4* __restrict__ row =
        reinterpret_cast<const float4*>(x + (size_t)b * SEQ * FILT);

    const float4 ninf = make_float4(-CUDART_INF_F, -CUDART_INF_F,
                                    -CUDART_INF_F, -CUDART_INF_F);
    float4 m0 = ninf, m1 = ninf, m2 = ninf;

    // Each thread covers positions s = 4*i + p for i in [0,64): warp-uniform s,
    // contiguous 512B per warp per load, 4KB per CTA per iteration.
    #pragma unroll 4
    for (int i = 0; i < SEQ / 4; ++i) {
        const int s = i * 4 + p;
        const float4 v = __ldg(&row[s * (FILT / 4) + g]);
        const int seg = (s > c1) + (s > c2);   // warp-uniform
        if (seg == 0)      m0 = fmax4(m0, v);
        else if (seg == 1) m1 = fmax4(m1, v);
        else               m2 = fmax4(m2, v);
    }

    // Reduce the 4 position-partials (threads p=0..3) per filter group.
    __shared__ float4 red[3][256];   // 12 KB
    red[0][t] = m0;
    red[1][t] = m1;
    red[2][t] = m2;
    __syncthreads();

    if (t < 192) {
        const int seg = t >> 6;
        const int gg  = t & 63;
        float4 r = fmax4(fmax4(red[seg][gg],       red[seg][64 + gg]),
                         fmax4(red[seg][128 + gg], red[seg][192 + gg]));
        float4* __restrict__ o =
            reinterpret_cast<float4*>(out + (size_t)b * 3 * FILT + seg * FILT);
        o[gg] = r;
    }
}

extern "C" void kernel_launch(void* const* d_in, const int* in_sizes, int n_in,
                              void* d_out, int out_size)
{
    const float* x  = (const float*)d_in[0];
    const int*   e1 = (const int*)d_in[1];
    const int*   e2 = (const int*)d_in[2];
    float*       o  = (float*)d_out;

    piecewise_maxpool_kernel<<<BATCH, 256>>>(x, e1, e2, o);
}